// round 11
// baseline (speedup 1.0000x reference)
#include <cuda_runtime.h>
#include <cuda_bf16.h>
#include <cstdint>

typedef uint32_t u32;

#define CL 8
#define NCTA 128
#define THREADS 512
#define T_LEN 512
#define SA 264                  // A row stride in halves (528 B)
#define MST 132                 // stage row stride in floats

// ---- smem byte offsets ----
#define OFF_AHI 0
#define OFF_ALO 67584           // 128*528
#define OFF_B   135168          // 4 tiles [G][p]{hi 8448 | lo 8448} stride 16896
#define OFF_ST  202752          // 2 groups x 16*132*4 = 8448 each
#define OFF_MBAR 219648
#define SMEM_BYTES 219680

// ---- device scratch ----
__device__ __align__(16) __nv_bfloat16 g_Apack[CL][2][128*SA];
__device__ float g_wih[CL*128];        // [(r*32+hid)*4+g]
__device__ float g_bias[CL*128];
__device__ float g_tsT[T_LEN*512];     // [t][b]
__device__ float g_part[CL*512];

// ---- asm helpers ----
__device__ __forceinline__ u32 smem_u32(const void* p){
    u32 a;
    asm("{ .reg .u64 t; cvta.to.shared.u64 t, %1; cvt.u32.u64 %0, t; }" : "=r"(a) : "l"(p));
    return a;
}
#define LDSM4(R, addr) \
    asm volatile("ldmatrix.sync.aligned.m8n8.x4.shared.b16 {%0,%1,%2,%3}, [%4];" \
        : "=r"((R)[0]), "=r"((R)[1]), "=r"((R)[2]), "=r"((R)[3]) : "r"(addr))
#define MBAR_INIT(addr, count) \
    asm volatile("mbarrier.init.shared.b64 [%0], %1;" :: "r"(addr), "r"(count) : "memory")
#define BAR_SYNC(id)   asm volatile("bar.sync %0, 512;"   :: "r"(id) : "memory")
#define BAR_ARRIVE(id) asm volatile("bar.arrive %0, 512;" :: "r"(id) : "memory")
__device__ __forceinline__ u32 mapa_r(u32 addr, u32 rank){
    u32 r; asm("mapa.shared::cluster.u32 %0, %1, %2;" : "=r"(r) : "r"(addr), "r"(rank)); return r;
}
#define STSC32(addr, v) \
    asm volatile("st.shared::cluster.u32 [%0], %1;" :: "r"(addr), "r"(v) : "memory")
#define MBAR_ARRIVE_REL(addr) \
    asm volatile("mbarrier.arrive.release.cluster.shared::cluster.b64 _, [%0];" \
                 :: "r"(addr) : "memory")
__device__ __forceinline__ void mbar_wait(u32 mbar, u32 parity){
    asm volatile(
        "{\n\t.reg .pred P;\n\t"
        "W_%=:\n\t"
        "mbarrier.try_wait.parity.acquire.cluster.shared::cta.b64 P, [%0], %1, 0x989680;\n\t"
        "@!P bra W_%=;\n\t}"
        :: "r"(mbar), "r"(parity) : "memory");
}
__device__ __forceinline__ void mma_bf16(float* d, const u32* a, const u32* b){
    asm volatile(
        "mma.sync.aligned.m16n8k16.row.col.f32.bf16.bf16.f32 "
        "{%0,%1,%2,%3}, {%4,%5,%6,%7}, {%8,%9}, {%0,%1,%2,%3};"
        : "+f"(d[0]), "+f"(d[1]), "+f"(d[2]), "+f"(d[3])
        : "r"(a[0]), "r"(a[1]), "r"(a[2]), "r"(a[3]), "r"(b[0]), "r"(b[1]));
}
__device__ __forceinline__ float sigf(float x){
    float e = __expf(-x); return __fdividef(1.f, 1.f + e);
}
__device__ __forceinline__ float tanha(float x){
    float ax = fabsf(x);
    float e = __expf(-2.f*ax);
    float t = __fdividef(1.f - e, 1.f + e);
    return copysignf(t, x);
}

// ---- prep ----
__global__ void prep_kernel(const float* __restrict__ ts, const float* __restrict__ W_ih,
                            const float* __restrict__ W_hh, const float* __restrict__ b_ih,
                            const float* __restrict__ b_hh){
    int i0 = blockIdx.x*blockDim.x + threadIdx.x, stride = gridDim.x*blockDim.x;
    for (int idx = i0; idx < CL*128*256; idx += stride){
        int k = idx & 255, m = (idx>>8)&127, r = idx>>15;
        int hid = m>>2, g = m&3;
        float w = W_hh[(g*256 + r*32 + hid)*256 + k];
        __nv_bfloat16 hi = __float2bfloat16(w);
        __nv_bfloat16 lo = __float2bfloat16(w - __bfloat162float(hi));
        g_Apack[r][0][m*SA + k] = hi;
        g_Apack[r][1][m*SA + k] = lo;
    }
    for (int idx = i0; idx < CL*128; idx += stride){
        int g = idx&3, hid = (idx>>2)&31, r = idx>>7;
        int j = g*256 + r*32 + hid;
        g_wih[idx]  = W_ih[j];
        g_bias[idx] = b_ih[j] + b_hh[j];
    }
    for (int idx = i0; idx < T_LEN*512; idx += stride){
        int b = idx & 511, t = idx >> 9;
        g_tsT[idx] = ts[b*T_LEN + t];
    }
}

__global__ void dummy_kernel(){}

// ---- main: cluster-8 LSTM, warp-specialized, DSMEM-direct h exchange ----
__global__ void __launch_bounds__(THREADS, 1) __cluster_dims__(CL, 1, 1)
lstm_mma(const float* __restrict__ Wout){
    extern __shared__ char smem[];
    u32 sb = smem_u32(smem);
    int tid = threadIdx.x, wid = tid >> 5, lane = tid & 31;
    uint32_t rk; asm("mov.u32 %0, %%cluster_ctarank;" : "=r"(rk));
    int B0 = (blockIdx.x >> 3) * 32;

    // init: A hi+lo -> smem, zero all 4 B tiles (h0 = 0), init mbarriers
    {
        const uint4* src = (const uint4*)&g_Apack[rk][0][0];
        uint4* dst = (uint4*)smem;
        for (int i = tid; i < 135168/16; i += THREADS) dst[i] = src[i];
        uint4* bz = (uint4*)(smem + OFF_B);
        for (int i = tid; i < 67584/16; i += THREADS) bz[i] = make_uint4(0,0,0,0);
    }
    if (tid == 0){ MBAR_INIT(sb + OFF_MBAR, 2048); MBAR_INIT(sb + OFF_MBAR + 8, 2048); }
    __syncthreads();
    asm volatile("barrier.cluster.arrive.aligned;" ::: "memory");
    asm volatile("barrier.cluster.wait.aligned;"   ::: "memory");

    if (wid < 8){
        // ================= GEMM role (warps 0-7) =================
        int w = wid;
        int q = lane >> 3, r = lane & 7;
        u32 aHiA = sb + (u32)((w*16 + (q&1)*8 + r)*528 + (q>>1)*16);
        u32 aLoA = aHiA + 67584;
        u32 bBase[2][2];
        #pragma unroll
        for (int G = 0; G < 2; ++G)
            #pragma unroll
            for (int p = 0; p < 2; ++p)
                bBase[G][p] = sb + OFF_B + (u32)((G*2+p)*16896)
                            + (u32)((((q>>1)*8 + r)*528) + (q&1)*16);
        int fg = lane >> 2, ft = lane & 3;
        int m0 = w*16 + fg, n0 = ft*2;

        for (int t = 0; t < T_LEN; ++t){
            int p = t & 1;
            #pragma unroll
            for (int G = 0; G < 2; ++G){
                BAR_SYNC(1 + G);                      // B tile ready
                float acc0[4] = {0,0,0,0}, acc1[4] = {0,0,0,0};
                u32 bHiA = bBase[G][p], bLoA = bHiA + 8448;
                #pragma unroll
                for (int kt = 0; kt < 16; ++kt){
                    u32 ah[4], al[4], bh[4], bl[4];
                    LDSM4(ah, aHiA + kt*32);
                    LDSM4(al, aLoA + kt*32);
                    LDSM4(bh, bHiA + kt*32);
                    LDSM4(bl, bLoA + kt*32);
                    mma_bf16(acc0, ah, bh);
                    mma_bf16(acc0, ah, bl);
                    mma_bf16(acc0, al, bh);
                    mma_bf16(acc1, ah, bh + 2);
                    mma_bf16(acc1, ah, bl + 2);
                    mma_bf16(acc1, al, bh + 2);
                }
                float* stG = (float*)(smem + OFF_ST + G*8448);
                stG[n0*MST + m0]           = acc0[0];
                stG[(n0+1)*MST + m0]       = acc0[1];
                stG[n0*MST + m0 + 8]       = acc0[2];
                stG[(n0+1)*MST + m0 + 8]   = acc0[3];
                stG[(n0+8)*MST + m0]       = acc1[0];
                stG[(n0+9)*MST + m0]       = acc1[1];
                stG[(n0+8)*MST + m0 + 8]   = acc1[2];
                stG[(n0+9)*MST + m0 + 8]   = acc1[3];
                BAR_ARRIVE(3 + G);                    // stage ready
            }
        }
    } else {
        // ================= EXCH role (warps 8-15) =================
        // thread -> (hid pair hp = e&15 -> hids 2hp,2hp+1 ; batch n16 = e>>4)
        int e = tid - 256;
        int hp = e & 15, n16 = e >> 4;
        int ghid0 = (int)rk*32 + hp*2;
        float4 wih0 = ((const float4*)g_wih )[rk*32 + hp*2];
        float4 wih1 = ((const float4*)g_wih )[rk*32 + hp*2 + 1];
        float4 bia0 = ((const float4*)g_bias)[rk*32 + hp*2];
        float4 bia1 = ((const float4*)g_bias)[rk*32 + hp*2 + 1];
        float creg[2][2] = {{0,0},{0,0}};
        float oacc[2] = {0,0};

        // precompute peer base addresses (B region and both mbarriers)
        u32 raB[CL], ma0[CL], ma1[CL];
        #pragma unroll
        for (int dr = 0; dr < CL; ++dr){
            raB[dr] = mapa_r(sb + OFF_B, (u32)dr);
            ma0[dr] = mapa_r(sb + OFF_MBAR, (u32)dr);
            ma1[dr] = mapa_r(sb + OFF_MBAR + 8, (u32)dr);
        }
        // per-thread constant part of the store offset: row n16, columns (ghid0, ghid0+1)
        u32 offc = (u32)(n16*528 + ghid0*2);

        BAR_ARRIVE(1); BAR_ARRIVE(2);                // prime B_ready (tiles zeroed)

        for (int t = 0; t < T_LEN; ++t){
            int wp = t & 1, p1 = wp ^ 1;
            float2 wo = *(const float2*)(Wout + t*256 + ghid0);
            float xv[2];
            xv[0] = g_tsT[t*512 + B0 + n16];
            xv[1] = g_tsT[t*512 + B0 + 16 + n16];

            #pragma unroll
            for (int G = 0; G < 2; ++G){
                u32 mbar = sb + OFF_MBAR + G*8;
                BAR_SYNC(3 + G);                      // stage ready
                const float* stG = (const float*)(smem + OFF_ST + G*8448);
                float4 gq0 = *(const float4*)(stG + n16*MST + hp*8);
                float4 gq1 = *(const float4*)(stG + n16*MST + hp*8 + 4);
                float x = xv[G];
                // hid 0 of pair
                float gi0 = gq0.x + fmaf(x, wih0.x, bia0.x);
                float gf0 = gq0.y + fmaf(x, wih0.y, bia0.y);
                float gg0 = gq0.z + fmaf(x, wih0.z, bia0.z);
                float go0 = gq0.w + fmaf(x, wih0.w, bia0.w);
                float c0  = sigf(gf0)*creg[G][0] + sigf(gi0)*tanha(gg0);
                creg[G][0] = c0;
                float h0  = sigf(go0)*tanha(c0);
                // hid 1 of pair
                float gi1 = gq1.x + fmaf(x, wih1.x, bia1.x);
                float gf1 = gq1.y + fmaf(x, wih1.y, bia1.y);
                float gg1 = gq1.z + fmaf(x, wih1.z, bia1.z);
                float go1 = gq1.w + fmaf(x, wih1.w, bia1.w);
                float c1  = sigf(gf1)*creg[G][1] + sigf(gi1)*tanha(gg1);
                creg[G][1] = c1;
                float h1  = sigf(go1)*tanha(c1);
                oacc[G] = fmaf(h0, wo.x, fmaf(h1, wo.y, oacc[G]));

                if (t < T_LEN-1){
                    __nv_bfloat16 h0b = __float2bfloat16(h0);
                    __nv_bfloat16 h1b = __float2bfloat16(h1);
                    __nv_bfloat16 l0b = __float2bfloat16(h0 - __bfloat162float(h0b));
                    __nv_bfloat16 l1b = __float2bfloat16(h1 - __bfloat162float(h1b));
                    u32 hiP = (u32)__bfloat16_as_ushort(h0b) | ((u32)__bfloat16_as_ushort(h1b) << 16);
                    u32 loP = (u32)__bfloat16_as_ushort(l0b) | ((u32)__bfloat16_as_ushort(l1b) << 16);
                    u32 off = (u32)((G*2 + p1)*16896) + offc;
                    #pragma unroll
                    for (int dr = 0; dr < CL; ++dr){
                        STSC32(raB[dr] + off,        hiP);
                        STSC32(raB[dr] + off + 8448, loP);
                    }
                    // per-thread release-arrive at every rank (count 2048)
                    #pragma unroll
                    for (int dr = 0; dr < CL; ++dr)
                        MBAR_ARRIVE_REL(G == 0 ? ma0[dr] : ma1[dr]);
                    mbar_wait(mbar, (u32)wp);
                    BAR_ARRIVE(1 + G);                // next B tile ready
                }
            }
        }
        // park oacc in stage smem for the epilogue
        {
            float* se = (float*)(smem + OFF_ST);
            se[(0*16 + n16)*17 + hp] = oacc[0];
            se[(1*16 + n16)*17 + hp] = oacc[1];
        }
    }

    // ---- epilogue ----
    __syncthreads();
    if (tid < 32){
        const float* se = (const float*)(smem + OFF_ST);
        float s = 0.f;
        for (int h2 = 0; h2 < 16; ++h2) s += se[tid*17 + h2];
        g_part[(size_t)rk*512 + B0 + tid] = s;
    }
    asm volatile("barrier.cluster.arrive.aligned;" ::: "memory");
    asm volatile("barrier.cluster.wait.aligned;"   ::: "memory");
}

// ---- finish ----
__global__ void finish_kernel(const float* __restrict__ b_out, float* __restrict__ out){
    int b = blockIdx.x * blockDim.x + threadIdx.x;
    if (b < 512){
        float s = b_out[0];
        #pragma unroll
        for (int r = 0; r < CL; ++r) s += g_part[r*512 + b];
        out[b] = s;
    }
}

extern "C" void kernel_launch(void* const* d_in, const int* in_sizes, int n_in,
                              void* d_out, int out_size){
    const float* ts    = (const float*)d_in[0];
    const float* W_ih  = (const float*)d_in[1];
    const float* W_hh  = (const float*)d_in[2];
    const float* b_ih  = (const float*)d_in[3];
    const float* b_hh  = (const float*)d_in[4];
    const float* W_out = (const float*)d_in[5];
    const float* b_out = (const float*)d_in[6];
    float* out = (float*)d_out;

    cudaFuncSetAttribute(lstm_mma, cudaFuncAttributeMaxDynamicSharedMemorySize, SMEM_BYTES);
    prep_kernel<<<256, 256>>>(ts, W_ih, W_hh, b_ih, b_hh);
    dummy_kernel<<<1, 32>>>();
    dummy_kernel<<<1, 32>>>();
    lstm_mma<<<NCTA, THREADS, SMEM_BYTES>>>(W_out);   // 16 clusters x 8 CTAs
    finish_kernel<<<2, 256>>>(b_out, out);
}

// round 12
// speedup vs baseline: 1.7166x; 1.7166x over previous
#include <cuda_runtime.h>
#include <cuda_bf16.h>
#include <cstdint>

typedef uint32_t u32;

#define CL 8
#define NCTA 128
#define THREADS 512
#define T_LEN 512
#define SA 264                  // A row stride in halves (528 B)
#define MST 132                 // stage row stride in floats

// ---- smem byte offsets ----
#define OFF_AHI 0
#define OFF_ALO 67584           // 128*528
#define OFF_B   135168          // 4 tiles [G][p]{hi 8448 | lo 8448} stride 16896
#define OFF_ST  202752          // 2 groups x 16*132*4 = 8448 each
#define OFF_MBAR 219648
#define SMEM_BYTES 219680

// ---- device scratch ----
__device__ __align__(16) __nv_bfloat16 g_Apack[CL][2][128*SA];
__device__ float g_wih[CL*128];        // [(r*32+hid)*4+g]
__device__ float g_bias[CL*128];
__device__ float g_tsT[T_LEN*512];     // [t][b]
__device__ u32   g_hq[2][512*256];     // [parity][b][k] packed (bf16_lo<<16)|bf16_hi
__device__ float g_part[CL*512];

// ---- asm helpers ----
__device__ __forceinline__ u32 smem_u32(const void* p){
    u32 a;
    asm("{ .reg .u64 t; cvta.to.shared.u64 t, %1; cvt.u32.u64 %0, t; }" : "=r"(a) : "l"(p));
    return a;
}
#define LDSM4(R, addr) \
    asm volatile("ldmatrix.sync.aligned.m8n8.x4.shared.b16 {%0,%1,%2,%3}, [%4];" \
        : "=r"((R)[0]), "=r"((R)[1]), "=r"((R)[2]), "=r"((R)[3]) : "r"(addr))
#define MBAR_INIT(addr, count) \
    asm volatile("mbarrier.init.shared.b64 [%0], %1;" :: "r"(addr), "r"(count) : "memory")
#define MBAR_ARRIVE_CLUSTER(addr, rank) \
    asm volatile("{\n\t.reg .b32 ra;\n\tmapa.shared::cluster.u32 ra, %0, %1;\n\t" \
                 "mbarrier.arrive.shared::cluster.b64 _, [ra];\n\t}" \
                 :: "r"(addr), "r"(rank) : "memory")
#define BAR_SYNC(id)   asm volatile("bar.sync %0, 512;"   :: "r"(id) : "memory")
#define BAR_ARRIVE(id) asm volatile("bar.arrive %0, 512;" :: "r"(id) : "memory")
__device__ __forceinline__ void mbar_wait(u32 mbar, u32 parity){
    asm volatile(
        "{\n\t.reg .pred P;\n\t"
        "W_%=:\n\t"
        "mbarrier.try_wait.parity.acquire.cluster.shared::cta.b64 P, [%0], %1, 0x989680;\n\t"
        "@!P bra W_%=;\n\t}"
        :: "r"(mbar), "r"(parity) : "memory");
}
__device__ __forceinline__ void mma_bf16(float* d, const u32* a, const u32* b){
    asm volatile(
        "mma.sync.aligned.m16n8k16.row.col.f32.bf16.bf16.f32 "
        "{%0,%1,%2,%3}, {%4,%5,%6,%7}, {%8,%9}, {%0,%1,%2,%3};"
        : "+f"(d[0]), "+f"(d[1]), "+f"(d[2]), "+f"(d[3])
        : "r"(a[0]), "r"(a[1]), "r"(a[2]), "r"(a[3]), "r"(b[0]), "r"(b[1]));
}
__device__ __forceinline__ float sigf(float x){
    float e = __expf(-x); return __fdividef(1.f, 1.f + e);
}
__device__ __forceinline__ float tanha(float x){
    float ax = fabsf(x);
    float e = __expf(-2.f*ax);
    float t = __fdividef(1.f - e, 1.f + e);
    return copysignf(t, x);
}

// ---- prep ----
__global__ void prep_kernel(const float* __restrict__ ts, const float* __restrict__ W_ih,
                            const float* __restrict__ W_hh, const float* __restrict__ b_ih,
                            const float* __restrict__ b_hh){
    int i0 = blockIdx.x*blockDim.x + threadIdx.x, stride = gridDim.x*blockDim.x;
    for (int idx = i0; idx < CL*128*256; idx += stride){
        int k = idx & 255, m = (idx>>8)&127, r = idx>>15;
        int hid = m>>2, g = m&3;
        float w = W_hh[(g*256 + r*32 + hid)*256 + k];
        __nv_bfloat16 hi = __float2bfloat16(w);
        __nv_bfloat16 lo = __float2bfloat16(w - __bfloat162float(hi));
        g_Apack[r][0][m*SA + k] = hi;
        g_Apack[r][1][m*SA + k] = lo;
    }
    for (int idx = i0; idx < CL*128; idx += stride){
        int g = idx&3, hid = (idx>>2)&31, r = idx>>7;
        int j = g*256 + r*32 + hid;
        g_wih[idx]  = W_ih[j];
        g_bias[idx] = b_ih[j] + b_hh[j];
    }
    for (int idx = i0; idx < T_LEN*512; idx += stride){
        int b = idx & 511, t = idx >> 9;
        g_tsT[idx] = ts[b*T_LEN + t];
    }
}

__global__ void dummy_kernel(){}

// ---- main: cluster-8 LSTM, warp-specialized, ONE rendezvous per step ----
__global__ void __launch_bounds__(THREADS, 1) __cluster_dims__(CL, 1, 1)
lstm_mma(const float* __restrict__ Wout){
    extern __shared__ char smem[];
    u32 sb = smem_u32(smem);
    int tid = threadIdx.x, wid = tid >> 5, lane = tid & 31;
    uint32_t rk; asm("mov.u32 %0, %%cluster_ctarank;" : "=r"(rk));
    int B0 = (blockIdx.x >> 3) * 32;

    // init: A hi+lo -> smem, zero all 4 B tiles (h0 = 0), init mbarrier
    {
        const uint4* src = (const uint4*)&g_Apack[rk][0][0];
        uint4* dst = (uint4*)smem;
        for (int i = tid; i < 135168/16; i += THREADS) dst[i] = src[i];
        uint4* bz = (uint4*)(smem + OFF_B);
        for (int i = tid; i < 67584/16; i += THREADS) bz[i] = make_uint4(0,0,0,0);
    }
    if (tid == 0) MBAR_INIT(sb + OFF_MBAR, 128);    // 8 warps x 8 ranks x 2 groups
    __syncthreads();
    asm volatile("barrier.cluster.arrive.aligned;" ::: "memory");
    asm volatile("barrier.cluster.wait.aligned;"   ::: "memory");

    if (wid < 8){
        // ================= GEMM role (warps 0-7) =================
        int w = wid;
        int q = lane >> 3, r = lane & 7;
        u32 aHiA = sb + (u32)((w*16 + (q&1)*8 + r)*528 + (q>>1)*16);
        u32 aLoA = aHiA + 67584;
        u32 bBase[2][2];
        #pragma unroll
        for (int G = 0; G < 2; ++G)
            #pragma unroll
            for (int p = 0; p < 2; ++p)
                bBase[G][p] = sb + OFF_B + (u32)((G*2+p)*16896)
                            + (u32)((((q>>1)*8 + r)*528) + (q&1)*16);
        int fg = lane >> 2, ft = lane & 3;
        int m0 = w*16 + fg, n0 = ft*2;

        for (int t = 0; t < T_LEN; ++t){
            int p = t & 1;
            BAR_SYNC(1);                              // both B tiles ready
            #pragma unroll
            for (int G = 0; G < 2; ++G){
                float acc0[4] = {0,0,0,0}, acc1[4] = {0,0,0,0};
                u32 bHiA = bBase[G][p], bLoA = bHiA + 8448;
                #pragma unroll
                for (int kt = 0; kt < 16; ++kt){
                    u32 ah[4], al[4], bh[4], bl[4];
                    LDSM4(ah, aHiA + kt*32);
                    LDSM4(al, aLoA + kt*32);
                    LDSM4(bh, bHiA + kt*32);
                    LDSM4(bl, bLoA + kt*32);
                    mma_bf16(acc0, ah, bh);
                    mma_bf16(acc0, ah, bl);
                    mma_bf16(acc0, al, bh);
                    mma_bf16(acc1, ah, bh + 2);
                    mma_bf16(acc1, ah, bl + 2);
                    mma_bf16(acc1, al, bh + 2);
                }
                float* stG = (float*)(smem + OFF_ST + G*8448);
                stG[n0*MST + m0]           = acc0[0];
                stG[(n0+1)*MST + m0]       = acc0[1];
                stG[n0*MST + m0 + 8]       = acc0[2];
                stG[(n0+1)*MST + m0 + 8]   = acc0[3];
                stG[(n0+8)*MST + m0]       = acc1[0];
                stG[(n0+9)*MST + m0]       = acc1[1];
                stG[(n0+8)*MST + m0 + 8]   = acc1[2];
                stG[(n0+9)*MST + m0 + 8]   = acc1[3];
                BAR_ARRIVE(3 + G);                    // stage(G) ready
            }
        }
    } else {
        // ================= EXCH role (warps 8-15) =================
        int e = tid - 256;
        int hid = e & 31, bb = e >> 5;               // 2 batches: bb*2, bb*2+1
        int ghid = (int)rk*32 + hid;
        float4 wih = ((const float4*)g_wih )[rk*32 + hid];
        float4 bia = ((const float4*)g_bias)[rk*32 + hid];
        float creg[2][2] = {{0,0},{0,0}};
        float oacc[2][2] = {{0,0},{0,0}};
        int rn = e & 15, rks = e >> 4;               // rebuild: row, 16-k slice
        u32 mbar = sb + OFF_MBAR;

        BAR_ARRIVE(1);                               // prime B_ready (tiles zeroed)

        for (int t = 0; t < T_LEN; ++t){
            int wp = t & 1, p1 = wp ^ 1;
            float wo = Wout[t*256 + ghid];
            float xv[2][2];
            #pragma unroll
            for (int G = 0; G < 2; ++G)
                #pragma unroll
                for (int j = 0; j < 2; ++j)
                    xv[G][j] = g_tsT[t*512 + B0 + G*16 + bb*2 + j];

            // ---- act both groups, arriving early after each ----
            #pragma unroll
            for (int G = 0; G < 2; ++G){
                BAR_SYNC(3 + G);                      // stage(G) ready
                const float* stG = (const float*)(smem + OFF_ST + G*8448);
                #pragma unroll
                for (int j = 0; j < 2; ++j){
                    int b = bb*2 + j;
                    float4 gq = *(const float4*)(stG + b*MST + hid*4);
                    float x = xv[G][j];
                    float gi = gq.x + fmaf(x, wih.x, bia.x);
                    float gf = gq.y + fmaf(x, wih.y, bia.y);
                    float gg = gq.z + fmaf(x, wih.z, bia.z);
                    float go = gq.w + fmaf(x, wih.w, bia.w);
                    float c  = sigf(gf)*creg[G][j] + sigf(gi)*tanha(gg);
                    creg[G][j] = c;
                    float h  = sigf(go)*tanha(c);
                    oacc[G][j] = fmaf(h, wo, oacc[G][j]);
                    __nv_bfloat16 hb = __float2bfloat16(h);
                    __nv_bfloat16 lb = __float2bfloat16(h - __bfloat162float(hb));
                    g_hq[wp][(size_t)(B0 + G*16 + b)*256 + ghid] =
                        ((u32)__bfloat16_as_ushort(lb) << 16) | (u32)__bfloat16_as_ushort(hb);
                }
                if (t < T_LEN-1){
                    __syncwarp();                     // order warp's STGs before release
                    if (lane == 0){
                        #pragma unroll
                        for (int dr = 0; dr < CL; ++dr) MBAR_ARRIVE_CLUSTER(mbar, dr);
                    }
                }
            }

            // ---- single rendezvous + batched rebuild of BOTH tiles ----
            if (t < T_LEN-1){
                mbar_wait(mbar, (u32)wp);
                const uint4* s0 = (const uint4*)(g_hq[wp] + (size_t)(B0 + rn)*256 + rks*16);
                const uint4* s1 = (const uint4*)(g_hq[wp] + (size_t)(B0 + 16 + rn)*256 + rks*16);
                uint4 q0 = __ldcg(s0),   q1 = __ldcg(s0+1), q2 = __ldcg(s0+2), q3 = __ldcg(s0+3);
                uint4 r0 = __ldcg(s1),   r1 = __ldcg(s1+1), r2 = __ldcg(s1+2), r3 = __ldcg(s1+3);
                uint4 hiA, loA, hiB, loB;
                char* bt0 = smem + OFF_B + (0*2 + p1)*16896 + rn*528 + rks*32;
                char* bt1 = smem + OFF_B + (1*2 + p1)*16896 + rn*528 + rks*32;
                // G0
                hiA.x = __byte_perm(q0.x, q0.y, 0x5410); hiA.y = __byte_perm(q0.z, q0.w, 0x5410);
                hiA.z = __byte_perm(q1.x, q1.y, 0x5410); hiA.w = __byte_perm(q1.z, q1.w, 0x5410);
                loA.x = __byte_perm(q0.x, q0.y, 0x7632); loA.y = __byte_perm(q0.z, q0.w, 0x7632);
                loA.z = __byte_perm(q1.x, q1.y, 0x7632); loA.w = __byte_perm(q1.z, q1.w, 0x7632);
                hiB.x = __byte_perm(q2.x, q2.y, 0x5410); hiB.y = __byte_perm(q2.z, q2.w, 0x5410);
                hiB.z = __byte_perm(q3.x, q3.y, 0x5410); hiB.w = __byte_perm(q3.z, q3.w, 0x5410);
                loB.x = __byte_perm(q2.x, q2.y, 0x7632); loB.y = __byte_perm(q2.z, q2.w, 0x7632);
                loB.z = __byte_perm(q3.x, q3.y, 0x7632); loB.w = __byte_perm(q3.z, q3.w, 0x7632);
                *(uint4*)(bt0)           = hiA;
                *(uint4*)(bt0 + 16)      = hiB;
                *(uint4*)(bt0 + 8448)    = loA;
                *(uint4*)(bt0 + 8448+16) = loB;
                // G1
                hiA.x = __byte_perm(r0.x, r0.y, 0x5410); hiA.y = __byte_perm(r0.z, r0.w, 0x5410);
                hiA.z = __byte_perm(r1.x, r1.y, 0x5410); hiA.w = __byte_perm(r1.z, r1.w, 0x5410);
                loA.x = __byte_perm(r0.x, r0.y, 0x7632); loA.y = __byte_perm(r0.z, r0.w, 0x7632);
                loA.z = __byte_perm(r1.x, r1.y, 0x7632); loA.w = __byte_perm(r1.z, r1.w, 0x7632);
                hiB.x = __byte_perm(r2.x, r2.y, 0x5410); hiB.y = __byte_perm(r2.z, r2.w, 0x5410);
                hiB.z = __byte_perm(r3.x, r3.y, 0x5410); hiB.w = __byte_perm(r3.z, r3.w, 0x5410);
                loB.x = __byte_perm(r2.x, r2.y, 0x7632); loB.y = __byte_perm(r2.z, r2.w, 0x7632);
                loB.z = __byte_perm(r3.x, r3.y, 0x7632); loB.w = __byte_perm(r3.z, r3.w, 0x7632);
                *(uint4*)(bt1)           = hiA;
                *(uint4*)(bt1 + 16)      = hiB;
                *(uint4*)(bt1 + 8448)    = loA;
                *(uint4*)(bt1 + 8448+16) = loB;
                BAR_ARRIVE(1);                        // both next-step B tiles ready
            }
        }
        // park oacc in stage smem for the epilogue (roles re-converge below)
        {
            float* se = (float*)(smem + OFF_ST);
            se[(0*16 + bb*2 + 0)*33 + hid] = oacc[0][0];
            se[(0*16 + bb*2 + 1)*33 + hid] = oacc[0][1];
            se[(1*16 + bb*2 + 0)*33 + hid] = oacc[1][0];
            se[(1*16 + bb*2 + 1)*33 + hid] = oacc[1][1];
        }
    }

    // ---- epilogue ----
    __syncthreads();
    if (tid < 32){
        const float* se = (const float*)(smem + OFF_ST);
        float s = 0.f;
        for (int h2 = 0; h2 < 32; ++h2) s += se[tid*33 + h2];
        g_part[(size_t)rk*512 + B0 + tid] = s;
    }
    asm volatile("barrier.cluster.arrive.aligned;" ::: "memory");
    asm volatile("barrier.cluster.wait.aligned;"   ::: "memory");
}

// ---- finish ----
__global__ void finish_kernel(const float* __restrict__ b_out, float* __restrict__ out){
    int b = blockIdx.x * blockDim.x + threadIdx.x;
    if (b < 512){
        float s = b_out[0];
        #pragma unroll
        for (int r = 0; r < CL; ++r) s += g_part[r*512 + b];
        out[b] = s;
    }
}

extern "C" void kernel_launch(void* const* d_in, const int* in_sizes, int n_in,
                              void* d_out, int out_size){
    const float* ts    = (const float*)d_in[0];
    const float* W_ih  = (const float*)d_in[1];
    const float* W_hh  = (const float*)d_in[2];
    const float* b_ih  = (const float*)d_in[3];
    const float* b_hh  = (const float*)d_in[4];
    const float* W_out = (const float*)d_in[5];
    const float* b_out = (const float*)d_in[6];
    float* out = (float*)d_out;

    cudaFuncSetAttribute(lstm_mma, cudaFuncAttributeMaxDynamicSharedMemorySize, SMEM_BYTES);
    prep_kernel<<<256, 256>>>(ts, W_ih, W_hh, b_ih, b_hh);
    dummy_kernel<<<1, 32>>>();
    dummy_kernel<<<1, 32>>>();
    lstm_mma<<<NCTA, THREADS, SMEM_BYTES>>>(W_out);   // 16 clusters x 8 CTAs
    finish_kernel<<<2, 256>>>(b_out, out);
}

// round 13
// speedup vs baseline: 2.8847x; 1.6804x over previous
#include <cuda_runtime.h>
#include <cuda_fp16.h>
#include <cstdint>

typedef uint32_t u32;

#define CL 8
#define NCTA 128
#define THREADS 512
#define T_LEN 512
#define SA 264                  // A row stride in halves (528 B)
#define MST 132                 // stage row stride in floats

// ---- smem byte offsets ----
#define OFF_AHI 0
#define OFF_ALO 67584           // 128*528
#define OFF_B   135168          // 4 tiles [G][p] single fp16 plane, 8448 each
#define OFF_ST  168960          // 2 groups x 16*132*4 = 8448 each
#define OFF_MBAR 185856
#define SMEM_BYTES 185888

// ---- device scratch ----
__device__ __align__(16) __half g_Apack[CL][2][128*SA];   // [rank][hi/lo fp16 W]
__device__ float g_wih[CL*128];        // [(r*32+hid)*4+g]
__device__ float g_bias[CL*128];
__device__ float g_tsT[T_LEN*512];     // [t][b]
__device__ __align__(16) __half g_hq[2][512*256];  // [parity][b][k] fp16 h
__device__ float g_part[CL*512];

// ---- asm helpers ----
__device__ __forceinline__ u32 smem_u32(const void* p){
    u32 a;
    asm("{ .reg .u64 t; cvta.to.shared.u64 t, %1; cvt.u32.u64 %0, t; }" : "=r"(a) : "l"(p));
    return a;
}
#define LDSM4(R, addr) \
    asm volatile("ldmatrix.sync.aligned.m8n8.x4.shared.b16 {%0,%1,%2,%3}, [%4];" \
        : "=r"((R)[0]), "=r"((R)[1]), "=r"((R)[2]), "=r"((R)[3]) : "r"(addr))
#define MBAR_INIT(addr, count) \
    asm volatile("mbarrier.init.shared.b64 [%0], %1;" :: "r"(addr), "r"(count) : "memory")
#define MBAR_ARRIVE_CLUSTER(addr, rank) \
    asm volatile("{\n\t.reg .b32 ra;\n\tmapa.shared::cluster.u32 ra, %0, %1;\n\t" \
                 "mbarrier.arrive.shared::cluster.b64 _, [ra];\n\t}" \
                 :: "r"(addr), "r"(rank) : "memory")
#define BAR_SYNC(id)   asm volatile("bar.sync %0, 512;"   :: "r"(id) : "memory")
#define BAR_ARRIVE(id) asm volatile("bar.arrive %0, 512;" :: "r"(id) : "memory")
__device__ __forceinline__ void mbar_wait(u32 mbar, u32 parity){
    asm volatile(
        "{\n\t.reg .pred P;\n\t"
        "W_%=:\n\t"
        "mbarrier.try_wait.parity.acquire.cluster.shared::cta.b64 P, [%0], %1, 0x989680;\n\t"
        "@!P bra W_%=;\n\t}"
        :: "r"(mbar), "r"(parity) : "memory");
}
__device__ __forceinline__ void mma_f16(float* d, const u32* a, const u32* b){
    asm volatile(
        "mma.sync.aligned.m16n8k16.row.col.f32.f16.f16.f32 "
        "{%0,%1,%2,%3}, {%4,%5,%6,%7}, {%8,%9}, {%0,%1,%2,%3};"
        : "+f"(d[0]), "+f"(d[1]), "+f"(d[2]), "+f"(d[3])
        : "r"(a[0]), "r"(a[1]), "r"(a[2]), "r"(a[3]), "r"(b[0]), "r"(b[1]));
}
__device__ __forceinline__ float sigf(float x){
    float e = __expf(-x); return __fdividef(1.f, 1.f + e);
}
__device__ __forceinline__ float tanha(float x){
    float ax = fabsf(x);
    float e = __expf(-2.f*ax);
    float t = __fdividef(1.f - e, 1.f + e);
    return copysignf(t, x);
}

// ---- prep: W -> fp16 hi/lo split in padded [m][k] layout ----
__global__ void prep_kernel(const float* __restrict__ ts, const float* __restrict__ W_ih,
                            const float* __restrict__ W_hh, const float* __restrict__ b_ih,
                            const float* __restrict__ b_hh){
    int i0 = blockIdx.x*blockDim.x + threadIdx.x, stride = gridDim.x*blockDim.x;
    for (int idx = i0; idx < CL*128*256; idx += stride){
        int k = idx & 255, m = (idx>>8)&127, r = idx>>15;
        int hid = m>>2, g = m&3;
        float w = W_hh[(g*256 + r*32 + hid)*256 + k];
        __half hi = __float2half_rn(w);
        __half lo = __float2half_rn(w - __half2float(hi));
        g_Apack[r][0][m*SA + k] = hi;
        g_Apack[r][1][m*SA + k] = lo;
    }
    for (int idx = i0; idx < CL*128; idx += stride){
        int g = idx&3, hid = (idx>>2)&31, r = idx>>7;
        int j = g*256 + r*32 + hid;
        g_wih[idx]  = W_ih[j];
        g_bias[idx] = b_ih[j] + b_hh[j];
    }
    for (int idx = i0; idx < T_LEN*512; idx += stride){
        int b = idx & 511, t = idx >> 9;
        g_tsT[idx] = ts[b*T_LEN + t];
    }
}

__global__ void dummy_kernel(){}

// ---- main: cluster-8 LSTM, warp-specialized, fp16 2-pass GEMM ----
__global__ void __launch_bounds__(THREADS, 1) __cluster_dims__(CL, 1, 1)
lstm_mma(const float* __restrict__ Wout){
    extern __shared__ char smem[];
    u32 sb = smem_u32(smem);
    int tid = threadIdx.x, wid = tid >> 5, lane = tid & 31;
    uint32_t rk; asm("mov.u32 %0, %%cluster_ctarank;" : "=r"(rk));
    int B0 = (blockIdx.x >> 3) * 32;

    // init: A hi+lo -> smem, zero all 4 B tiles (h0 = 0), init mbarriers
    {
        const uint4* src = (const uint4*)&g_Apack[rk][0][0];
        uint4* dst = (uint4*)smem;
        for (int i = tid; i < 135168/16; i += THREADS) dst[i] = src[i];
        uint4* bz = (uint4*)(smem + OFF_B);
        for (int i = tid; i < 33792/16; i += THREADS) bz[i] = make_uint4(0,0,0,0);
    }
    if (tid == 0){ MBAR_INIT(sb + OFF_MBAR, 64); MBAR_INIT(sb + OFF_MBAR + 8, 64); }
    __syncthreads();
    asm volatile("barrier.cluster.arrive.aligned;" ::: "memory");
    asm volatile("barrier.cluster.wait.aligned;"   ::: "memory");

    if (wid < 8){
        // ================= GEMM role (warps 0-7) =================
        int w = wid;
        int q = lane >> 3, r = lane & 7;
        u32 aHiA = sb + (u32)((w*16 + (q&1)*8 + r)*528 + (q>>1)*16);
        u32 aLoA = aHiA + 67584;
        u32 bBase[2][2];
        #pragma unroll
        for (int G = 0; G < 2; ++G)
            #pragma unroll
            for (int p = 0; p < 2; ++p)
                bBase[G][p] = sb + OFF_B + (u32)((G*2+p)*8448)
                            + (u32)((((q>>1)*8 + r)*528) + (q&1)*16);
        int fg = lane >> 2, ft = lane & 3;
        int m0 = w*16 + fg, n0 = ft*2;

        for (int t = 0; t < T_LEN; ++t){
            int p = t & 1;
            #pragma unroll
            for (int G = 0; G < 2; ++G){
                BAR_SYNC(1 + G);                      // B tile ready
                float acc0[4] = {0,0,0,0}, acc1[4] = {0,0,0,0};
                u32 bA = bBase[G][p];
                #pragma unroll
                for (int kt = 0; kt < 16; ++kt){
                    u32 ah[4], al[4], bh[4];
                    LDSM4(ah, aHiA + kt*32);
                    LDSM4(al, aLoA + kt*32);
                    LDSM4(bh, bA + kt*32);
                    mma_f16(acc0, ah, bh);        // Whi*H  (n 0-7)
                    mma_f16(acc0, al, bh);        // Wlo*H
                    mma_f16(acc1, ah, bh + 2);    // n 8-15
                    mma_f16(acc1, al, bh + 2);
                }
                float* stG = (float*)(smem + OFF_ST + G*8448);
                stG[n0*MST + m0]           = acc0[0];
                stG[(n0+1)*MST + m0]       = acc0[1];
                stG[n0*MST + m0 + 8]       = acc0[2];
                stG[(n0+1)*MST + m0 + 8]   = acc0[3];
                stG[(n0+8)*MST + m0]       = acc1[0];
                stG[(n0+9)*MST + m0]       = acc1[1];
                stG[(n0+8)*MST + m0 + 8]   = acc1[2];
                stG[(n0+9)*MST + m0 + 8]   = acc1[3];
                BAR_ARRIVE(3 + G);                    // stage ready
            }
        }
    } else {
        // ================= EXCH role (warps 8-15) =================
        int e = tid - 256;
        int hid = e & 31, bb = e >> 5;               // 2 batches: bb*2, bb*2+1
        int ghid = (int)rk*32 + hid;
        float4 wih = ((const float4*)g_wih )[rk*32 + hid];
        float4 bia = ((const float4*)g_bias)[rk*32 + hid];
        float creg[2][2] = {{0,0},{0,0}};
        float oacc[2][2] = {{0,0},{0,0}};
        int rn = e & 15, rks = e >> 4;               // rebuild: row, 16-k slice

        BAR_ARRIVE(1); BAR_ARRIVE(2);                // prime B_ready (tiles zeroed)

        for (int t = 0; t < T_LEN; ++t){
            int wp = t & 1, p1 = wp ^ 1;
            float wo = Wout[t*256 + ghid];
            float xv[2][2];
            #pragma unroll
            for (int G = 0; G < 2; ++G)
                #pragma unroll
                for (int j = 0; j < 2; ++j)
                    xv[G][j] = g_tsT[t*512 + B0 + G*16 + bb*2 + j];

            #pragma unroll
            for (int G = 0; G < 2; ++G){
                u32 mbar = sb + OFF_MBAR + G*8;
                BAR_SYNC(3 + G);                      // stage ready
                const float* stG = (const float*)(smem + OFF_ST + G*8448);
                #pragma unroll
                for (int j = 0; j < 2; ++j){
                    int b = bb*2 + j;
                    float4 gq = *(const float4*)(stG + b*MST + hid*4);
                    float x = xv[G][j];
                    float gi = gq.x + fmaf(x, wih.x, bia.x);
                    float gf = gq.y + fmaf(x, wih.y, bia.y);
                    float gg = gq.z + fmaf(x, wih.z, bia.z);
                    float go = gq.w + fmaf(x, wih.w, bia.w);
                    float c  = sigf(gf)*creg[G][j] + sigf(gi)*tanha(gg);
                    creg[G][j] = c;
                    float h  = sigf(go)*tanha(c);
                    oacc[G][j] = fmaf(h, wo, oacc[G][j]);
                    g_hq[wp][(size_t)(B0 + G*16 + b)*256 + ghid] = __float2half_rn(h);
                }
                if (t < T_LEN-1){
                    __syncwarp();                     // order warp's STGs before release
                    if (lane == 0){
                        #pragma unroll
                        for (int dr = 0; dr < CL; ++dr) MBAR_ARRIVE_CLUSTER(mbar, dr);
                    }
                    mbar_wait(mbar, (u32)wp);
                    // rebuild: straight 32B copy, no deinterleave
                    const uint4* src = (const uint4*)(g_hq[wp] + (size_t)(B0 + G*16 + rn)*256 + rks*16);
                    uint4 v0 = __ldcg(src), v1 = __ldcg(src + 1);
                    char* bt = smem + OFF_B + (G*2 + p1)*8448 + rn*528 + rks*32;
                    *(uint4*)(bt)      = v0;
                    *(uint4*)(bt + 16) = v1;
                    BAR_ARRIVE(1 + G);                // next B tile ready
                }
            }
        }
        // park oacc in stage smem for the epilogue
        {
            float* se = (float*)(smem + OFF_ST);
            se[(0*16 + bb*2 + 0)*33 + hid] = oacc[0][0];
            se[(0*16 + bb*2 + 1)*33 + hid] = oacc[0][1];
            se[(1*16 + bb*2 + 0)*33 + hid] = oacc[1][0];
            se[(1*16 + bb*2 + 1)*33 + hid] = oacc[1][1];
        }
    }

    // ---- epilogue ----
    __syncthreads();
    if (tid < 32){
        const float* se = (const float*)(smem + OFF_ST);
        float s = 0.f;
        for (int h2 = 0; h2 < 32; ++h2) s += se[tid*33 + h2];
        g_part[(size_t)rk*512 + B0 + tid] = s;
    }
    asm volatile("barrier.cluster.arrive.aligned;" ::: "memory");
    asm volatile("barrier.cluster.wait.aligned;"   ::: "memory");
}

// ---- finish ----
__global__ void finish_kernel(const float* __restrict__ b_out, float* __restrict__ out){
    int b = blockIdx.x * blockDim.x + threadIdx.x;
    if (b < 512){
        float s = b_out[0];
        #pragma unroll
        for (int r = 0; r < CL; ++r) s += g_part[r*512 + b];
        out[b] = s;
    }
}

extern "C" void kernel_launch(void* const* d_in, const int* in_sizes, int n_in,
                              void* d_out, int out_size){
    const float* ts    = (const float*)d_in[0];
    const float* W_ih  = (const float*)d_in[1];
    const float* W_hh  = (const float*)d_in[2];
    const float* b_ih  = (const float*)d_in[3];
    const float* b_hh  = (const float*)d_in[4];
    const float* W_out = (const float*)d_in[5];
    const float* b_out = (const float*)d_in[6];
    float* out = (float*)d_out;

    cudaFuncSetAttribute(lstm_mma, cudaFuncAttributeMaxDynamicSharedMemorySize, SMEM_BYTES);
    prep_kernel<<<256, 256>>>(ts, W_ih, W_hh, b_ih, b_hh);
    dummy_kernel<<<1, 32>>>();
    dummy_kernel<<<1, 32>>>();
    lstm_mma<<<NCTA, THREADS, SMEM_BYTES>>>(W_out);   // 16 clusters x 8 CTAs
    finish_kernel<<<2, 256>>>(b_out, out);
}

// round 14
// speedup vs baseline: 3.3535x; 1.1625x over previous
#include <cuda_runtime.h>
#include <cuda_fp16.h>
#include <cstdint>

typedef uint32_t u32;

#define CL 8
#define NCTA 128
#define THREADS 512
#define T_LEN 512
#define SA 264                  // A row stride in halves (528 B)
#define MST 132                 // stage row stride in floats

// ---- smem byte offsets ----
#define OFF_A   0               // single fp16 W plane, 128*528 = 67584
#define OFF_B   67584           // 4 tiles [G][p] single fp16 plane, 8448 each
#define OFF_ST  101376          // 2 groups x 16*132*4 = 8448 each
#define OFF_MBAR 118272
#define SMEM_BYTES 118304

// ---- device scratch ----
__device__ __align__(16) __half g_Apack[CL][128*SA];   // [rank] fp16 W, [m][k] padded
__device__ float g_wih[CL*128];        // [(r*32+hid)*4+g]
__device__ float g_bias[CL*128];
__device__ float g_tsT[T_LEN*512];     // [t][b]
__device__ __align__(16) __half g_hq[2][512*256];  // [parity][b][k] fp16 h
__device__ float g_part[CL*512];

// ---- asm helpers ----
__device__ __forceinline__ u32 smem_u32(const void* p){
    u32 a;
    asm("{ .reg .u64 t; cvta.to.shared.u64 t, %1; cvt.u32.u64 %0, t; }" : "=r"(a) : "l"(p));
    return a;
}
#define LDSM4(R, addr) \
    asm volatile("ldmatrix.sync.aligned.m8n8.x4.shared.b16 {%0,%1,%2,%3}, [%4];" \
        : "=r"((R)[0]), "=r"((R)[1]), "=r"((R)[2]), "=r"((R)[3]) : "r"(addr))
#define MBAR_INIT(addr, count) \
    asm volatile("mbarrier.init.shared.b64 [%0], %1;" :: "r"(addr), "r"(count) : "memory")
#define MBAR_ARRIVE_CLUSTER(addr, rank) \
    asm volatile("{\n\t.reg .b32 ra;\n\tmapa.shared::cluster.u32 ra, %0, %1;\n\t" \
                 "mbarrier.arrive.shared::cluster.b64 _, [ra];\n\t}" \
                 :: "r"(addr), "r"(rank) : "memory")
#define BAR_SYNC(id)   asm volatile("bar.sync %0, 512;"   :: "r"(id) : "memory")
#define BAR_ARRIVE(id) asm volatile("bar.arrive %0, 512;" :: "r"(id) : "memory")
__device__ __forceinline__ void mbar_wait(u32 mbar, u32 parity){
    asm volatile(
        "{\n\t.reg .pred P;\n\t"
        "W_%=:\n\t"
        "mbarrier.try_wait.parity.acquire.cluster.shared::cta.b64 P, [%0], %1, 0x989680;\n\t"
        "@!P bra W_%=;\n\t}"
        :: "r"(mbar), "r"(parity) : "memory");
}
__device__ __forceinline__ void mma_f16(float* d, const u32* a, const u32* b){
    asm volatile(
        "mma.sync.aligned.m16n8k16.row.col.f32.f16.f16.f32 "
        "{%0,%1,%2,%3}, {%4,%5,%6,%7}, {%8,%9}, {%0,%1,%2,%3};"
        : "+f"(d[0]), "+f"(d[1]), "+f"(d[2]), "+f"(d[3])
        : "r"(a[0]), "r"(a[1]), "r"(a[2]), "r"(a[3]), "r"(b[0]), "r"(b[1]));
}
__device__ __forceinline__ float sigf(float x){
    float e = __expf(-x); return __fdividef(1.f, 1.f + e);
}
__device__ __forceinline__ float tanha(float x){
    float ax = fabsf(x);
    float e = __expf(-2.f*ax);
    float t = __fdividef(1.f - e, 1.f + e);
    return copysignf(t, x);
}

// ---- prep: W -> fp16 in padded [m][k] layout ----
__global__ void prep_kernel(const float* __restrict__ ts, const float* __restrict__ W_ih,
                            const float* __restrict__ W_hh, const float* __restrict__ b_ih,
                            const float* __restrict__ b_hh){
    int i0 = blockIdx.x*blockDim.x + threadIdx.x, stride = gridDim.x*blockDim.x;
    for (int idx = i0; idx < CL*128*256; idx += stride){
        int k = idx & 255, m = (idx>>8)&127, r = idx>>15;
        int hid = m>>2, g = m&3;
        float w = W_hh[(g*256 + r*32 + hid)*256 + k];
        g_Apack[r][m*SA + k] = __float2half_rn(w);
    }
    for (int idx = i0; idx < CL*128; idx += stride){
        int g = idx&3, hid = (idx>>2)&31, r = idx>>7;
        int j = g*256 + r*32 + hid;
        g_wih[idx]  = W_ih[j];
        g_bias[idx] = b_ih[j] + b_hh[j];
    }
    for (int idx = i0; idx < T_LEN*512; idx += stride){
        int b = idx & 511, t = idx >> 9;
        g_tsT[idx] = ts[b*T_LEN + t];
    }
}

__global__ void dummy_kernel(){}

// ---- main: cluster-8 LSTM, warp-specialized, fp16 1-pass GEMM ----
__global__ void __launch_bounds__(THREADS, 1) __cluster_dims__(CL, 1, 1)
lstm_mma(const float* __restrict__ Wout){
    extern __shared__ char smem[];
    u32 sb = smem_u32(smem);
    int tid = threadIdx.x, wid = tid >> 5, lane = tid & 31;
    uint32_t rk; asm("mov.u32 %0, %%cluster_ctarank;" : "=r"(rk));
    int B0 = (blockIdx.x >> 3) * 32;

    // init: A -> smem, zero all 4 B tiles (h0 = 0), init mbarriers
    {
        const uint4* src = (const uint4*)&g_Apack[rk][0];
        uint4* dst = (uint4*)smem;
        for (int i = tid; i < 67584/16; i += THREADS) dst[i] = src[i];
        uint4* bz = (uint4*)(smem + OFF_B);
        for (int i = tid; i < 33792/16; i += THREADS) bz[i] = make_uint4(0,0,0,0);
    }
    if (tid == 0){ MBAR_INIT(sb + OFF_MBAR, 64); MBAR_INIT(sb + OFF_MBAR + 8, 64); }
    __syncthreads();
    asm volatile("barrier.cluster.arrive.aligned;" ::: "memory");
    asm volatile("barrier.cluster.wait.aligned;"   ::: "memory");

    if (wid < 8){
        // ================= GEMM role (warps 0-7) =================
        int w = wid;
        int q = lane >> 3, r = lane & 7;
        u32 aA = sb + (u32)((w*16 + (q&1)*8 + r)*528 + (q>>1)*16);
        u32 bBase[2][2];
        #pragma unroll
        for (int G = 0; G < 2; ++G)
            #pragma unroll
            for (int p = 0; p < 2; ++p)
                bBase[G][p] = sb + OFF_B + (u32)((G*2+p)*8448)
                            + (u32)((((q>>1)*8 + r)*528) + (q&1)*16);
        int fg = lane >> 2, ft = lane & 3;
        int m0 = w*16 + fg, n0 = ft*2;

        for (int t = 0; t < T_LEN; ++t){
            int p = t & 1;
            #pragma unroll
            for (int G = 0; G < 2; ++G){
                BAR_SYNC(1 + G);                      // B tile ready
                float acc0[4] = {0,0,0,0}, acc1[4] = {0,0,0,0};
                u32 bA = bBase[G][p];
                #pragma unroll
                for (int kt = 0; kt < 16; ++kt){
                    u32 ah[4], bh[4];
                    LDSM4(ah, aA + kt*32);
                    LDSM4(bh, bA + kt*32);
                    mma_f16(acc0, ah, bh);        // n 0-7
                    mma_f16(acc1, ah, bh + 2);    // n 8-15
                }
                float* stG = (float*)(smem + OFF_ST + G*8448);
                stG[n0*MST + m0]           = acc0[0];
                stG[(n0+1)*MST + m0]       = acc0[1];
                stG[n0*MST + m0 + 8]       = acc0[2];
                stG[(n0+1)*MST + m0 + 8]   = acc0[3];
                stG[(n0+8)*MST + m0]       = acc1[0];
                stG[(n0+9)*MST + m0]       = acc1[1];
                stG[(n0+8)*MST + m0 + 8]   = acc1[2];
                stG[(n0+9)*MST + m0 + 8]   = acc1[3];
                BAR_ARRIVE(3 + G);                    // stage ready
            }
        }
    } else {
        // ================= EXCH role (warps 8-15) =================
        int e = tid - 256;
        int hid = e & 31, bb = e >> 5;               // 2 batches: bb*2, bb*2+1
        int ghid = (int)rk*32 + hid;
        float4 wih = ((const float4*)g_wih )[rk*32 + hid];
        float4 bia = ((const float4*)g_bias)[rk*32 + hid];
        float creg[2][2] = {{0,0},{0,0}};
        float oacc[2][2] = {{0,0},{0,0}};
        int rn = e & 15, rks = e >> 4;               // rebuild: row, 16-k slice

        BAR_ARRIVE(1); BAR_ARRIVE(2);                // prime B_ready (tiles zeroed)

        for (int t = 0; t < T_LEN; ++t){
            int wp = t & 1, p1 = wp ^ 1;
            float wo = Wout[t*256 + ghid];
            float xv[2][2];
            #pragma unroll
            for (int G = 0; G < 2; ++G)
                #pragma unroll
                for (int j = 0; j < 2; ++j)
                    xv[G][j] = g_tsT[t*512 + B0 + G*16 + bb*2 + j];

            #pragma unroll
            for (int G = 0; G < 2; ++G){
                u32 mbar = sb + OFF_MBAR + G*8;
                BAR_SYNC(3 + G);                      // stage ready
                const float* stG = (const float*)(smem + OFF_ST + G*8448);
                #pragma unroll
                for (int j = 0; j < 2; ++j){
                    int b = bb*2 + j;
                    float4 gq = *(const float4*)(stG + b*MST + hid*4);
                    float x = xv[G][j];
                    float gi = gq.x + fmaf(x, wih.x, bia.x);
                    float gf = gq.y + fmaf(x, wih.y, bia.y);
                    float gg = gq.z + fmaf(x, wih.z, bia.z);
                    float go = gq.w + fmaf(x, wih.w, bia.w);
                    float c  = sigf(gf)*creg[G][j] + sigf(gi)*tanha(gg);
                    creg[G][j] = c;
                    float h  = sigf(go)*tanha(c);
                    oacc[G][j] = fmaf(h, wo, oacc[G][j]);
                    g_hq[wp][(size_t)(B0 + G*16 + b)*256 + ghid] = __float2half_rn(h);
                }
                if (t < T_LEN-1){
                    __syncwarp();                     // order warp's STGs before release
                    if (lane == 0){
                        #pragma unroll
                        for (int dr = 0; dr < CL; ++dr) MBAR_ARRIVE_CLUSTER(mbar, dr);
                    }
                    mbar_wait(mbar, (u32)wp);
                    // rebuild: straight 32B copy
                    const uint4* src = (const uint4*)(g_hq[wp] + (size_t)(B0 + G*16 + rn)*256 + rks*16);
                    uint4 v0 = __ldcg(src), v1 = __ldcg(src + 1);
                    char* bt = smem + OFF_B + (G*2 + p1)*8448 + rn*528 + rks*32;
                    *(uint4*)(bt)      = v0;
                    *(uint4*)(bt + 16) = v1;
                    BAR_ARRIVE(1 + G);                // next B tile ready
                }
            }
        }
        // park oacc in stage smem for the epilogue
        {
            float* se = (float*)(smem + OFF_ST);
            se[(0*16 + bb*2 + 0)*33 + hid] = oacc[0][0];
            se[(0*16 + bb*2 + 1)*33 + hid] = oacc[0][1];
            se[(1*16 + bb*2 + 0)*33 + hid] = oacc[1][0];
            se[(1*16 + bb*2 + 1)*33 + hid] = oacc[1][1];
        }
    }

    // ---- epilogue ----
    __syncthreads();
    if (tid < 32){
        const float* se = (const float*)(smem + OFF_ST);
        float s = 0.f;
        for (int h2 = 0; h2 < 32; ++h2) s += se[tid*33 + h2];
        g_part[(size_t)rk*512 + B0 + tid] = s;
    }
    asm volatile("barrier.cluster.arrive.aligned;" ::: "memory");
    asm volatile("barrier.cluster.wait.aligned;"   ::: "memory");
}

// ---- finish ----
__global__ void finish_kernel(const float* __restrict__ b_out, float* __restrict__ out){
    int b = blockIdx.x * blockDim.x + threadIdx.x;
    if (b < 512){
        float s = b_out[0];
        #pragma unroll
        for (int r = 0; r < CL; ++r) s += g_part[r*512 + b];
        out[b] = s;
    }
}

extern "C" void kernel_launch(void* const* d_in, const int* in_sizes, int n_in,
                              void* d_out, int out_size){
    const float* ts    = (const float*)d_in[0];
    const float* W_ih  = (const float*)d_in[1];
    const float* W_hh  = (const float*)d_in[2];
    const float* b_ih  = (const float*)d_in[3];
    const float* b_hh  = (const float*)d_in[4];
    const float* W_out = (const float*)d_in[5];
    const float* b_out = (const float*)d_in[6];
    float* out = (float*)d_out;

    cudaFuncSetAttribute(lstm_mma, cudaFuncAttributeMaxDynamicSharedMemorySize, SMEM_BYTES);
    prep_kernel<<<256, 256>>>(ts, W_ih, W_hh, b_ih, b_hh);
    dummy_kernel<<<1, 32>>>();
    dummy_kernel<<<1, 32>>>();
    lstm_mma<<<NCTA, THREADS, SMEM_BYTES>>>(W_out);   // 16 clusters x 8 CTAs
    finish_kernel<<<2, 256>>>(b_out, out);
}